// round 3
// baseline (speedup 1.0000x reference)
#include <cuda_runtime.h>
#include <stdint.h>

// Problem constants (fixed shapes for this problem)
constexpr int S_DIM = 16384;   // s
constexpr int T_DIM = 8192;    // t
constexpr int B_DIM = 16;      // batch
constexpr int NH    = 16;      // top-k
constexpr int KEEP  = 24;      // candidates kept at each rebuild (margin over NH for sqrt ties)
constexpr int CAP   = 128;     // per-warp candidate buffer capacity
constexpr int TRIG  = 96;      // rebuild trigger (TRIG + 32 <= CAP)
constexpr unsigned FULLM = 0xFFFFFFFFu;

// Output layout (float32 concat of the tuple):
constexpr size_t OFF_XNEAR = 0;                               // [16][8192][16][1]
constexpr size_t OFF_IDIST = (size_t)B_DIM * T_DIM * NH;      // 2097152
constexpr size_t OFF_ILON  = OFF_IDIST + (size_t)T_DIM * NH;  // 2228224
constexpr size_t OFF_ILAT  = OFF_ILON  + (size_t)T_DIM * NH;  // 2359296

// Pack (nonnegative float value, index) into a u64 whose unsigned order is
// (value ascending, index ascending) — exactly jax.lax.top_k's stable order.
__device__ __forceinline__ unsigned long long pack_key(float v, unsigned idx) {
    return ((unsigned long long)__float_as_uint(v) << 32) | idx;
}

__device__ __forceinline__ unsigned long long warp_min64(unsigned long long v) {
    #pragma unroll
    for (int o = 16; o > 0; o >>= 1) {
        unsigned long long w = __shfl_xor_sync(FULLM, v, o);
        if (w < v) v = w;
    }
    return v;
}

// Warp-collective: select `rounds` smallest keys from buf[0..cnt), write them
// sorted ascending into buf[0..rounds). Returns the rounds-th smallest key.
// Keys are unique (distinct low-32 indices), so ownership resolution is exact.
__device__ __forceinline__ unsigned long long select_sorted(
    unsigned long long* buf, int cnt, int rounds, int lane)
{
    unsigned long long k[CAP / 32];
    unsigned long long lmin = ~0ull;
    #pragma unroll
    for (int q = 0; q < CAP / 32; q++) {
        int p = lane + 32 * q;
        k[q] = (p < cnt) ? buf[p] : ~0ull;
        if (k[q] < lmin) lmin = k[q];
    }
    unsigned long long g = ~0ull;
    for (int r = 0; r < rounds; r++) {
        g = warp_min64(lmin);
        if (lmin == g) {                 // unique owner (keys unique)
            unsigned long long nl = ~0ull;
            #pragma unroll
            for (int q = 0; q < CAP / 32; q++) {
                if (k[q] == g) k[q] = ~0ull;
                if (k[q] < nl) nl = k[q];
            }
            lmin = nl;
        }
        if (lane == 0) buf[r] = g;
    }
    __syncwarp();
    return g;
}

// Warp-collective append of passing elements into the candidate buffer.
// cnt/thr are warp-uniform registers. Rebuild keeps KEEP best and tightens thr.
// Max growth between rebuild checks: 32; 24 -> 56 -> 88 -> 120 <= CAP.
__device__ __forceinline__ void try_append(bool p, float v, unsigned idx,
    unsigned long long* buf, int& cnt, float& thr, int lane)
{
    unsigned m = __ballot_sync(FULLM, p);
    if (m == 0) return;
    if (p) buf[cnt + __popc(m & ((1u << lane) - 1u))] = pack_key(v, idx);
    cnt += __popc(m);
    if (cnt > TRIG) {
        __syncwarp();
        unsigned long long g = select_sorted(buf, cnt, KEEP, lane);
        cnt = KEEP;
        thr = __uint_as_float((unsigned)(g >> 32));   // KEEP-th best value; compare is inclusive
    }
}

__global__ __launch_bounds__(96)
void nn_topk_kernel(const float* __restrict__ x,
                    const float* __restrict__ dlon,
                    const float* __restrict__ dlat,
                    float* __restrict__ out)
{
    __shared__ unsigned long long sbuf[3][CAP];

    const int row  = blockIdx.x;
    const int warp = threadIdx.x >> 5;
    const int lane = threadIdx.x & 31;
    unsigned long long* buf = sbuf[warp];

    float thr = __int_as_float(0x7f800000);  // +inf: accept-all until first rebuild
    int cnt = 0;

    if (warp == 0) {
        // ---- criterion: euclidean distance (scan on squared distance) ----
        const float4* Pa = reinterpret_cast<const float4*>(dlon + (size_t)row * S_DIM);
        const float4* Pb = reinterpret_cast<const float4*>(dlat + (size_t)row * S_DIM);
        #pragma unroll 2
        for (int it = 0; it < S_DIM / 128; ++it) {
            float4 a = Pa[it * 32 + lane];
            float4 b = Pb[it * 32 + lane];
            float s0 = fmaf(a.x, a.x, b.x * b.x);
            float s1 = fmaf(a.y, a.y, b.y * b.y);
            float s2 = fmaf(a.z, a.z, b.z * b.z);
            float s3 = fmaf(a.w, a.w, b.w * b.w);
            bool p0 = s0 <= thr, p1 = s1 <= thr, p2 = s2 <= thr, p3 = s3 <= thr;
            unsigned base = (unsigned)(it * 128) + (unsigned)lane * 4u;
            if (__any_sync(FULLM, p0 | p1)) {
                try_append(p0, s0, base + 0u, buf, cnt, thr, lane);
                try_append(p1, s1, base + 1u, buf, cnt, thr, lane);
            }
            if (__any_sync(FULLM, p2 | p3)) {
                try_append(p2, s2, base + 2u, buf, cnt, thr, lane);
                try_append(p3, s3, base + 3u, buf, cnt, thr, lane);
            }
        }
        // Re-key survivors with exact IEEE sqrt so final order matches reference.
        __syncwarp();
        for (int p = lane; p < cnt; p += 32) {
            unsigned long long e = buf[p];
            float d = __fsqrt_rn(__uint_as_float((unsigned)(e >> 32)));
            buf[p] = pack_key(d, (unsigned)e);
        }
        __syncwarp();
        select_sorted(buf, cnt, NH, lane);   // buf[0..15] = final sorted keys

        // indices_dist (as float)
        if (lane < NH) {
            unsigned idx = (unsigned)buf[lane];
            out[OFF_IDIST + (size_t)row * NH + lane] = (float)idx;
        }
        __syncwarp();
        // x_nearest gather: out[b][row][j] = x[b][idx_j]   (e == 1)
        #pragma unroll
        for (int p = lane; p < B_DIM * NH; p += 32) {
            int b = p >> 4;
            int j = p & 15;
            unsigned idx = (unsigned)buf[j];
            out[OFF_XNEAR + (size_t)b * (T_DIM * NH) + (size_t)row * NH + j] =
                x[(size_t)b * S_DIM + idx];
        }
    } else {
        // ---- criterion: |d_lon| (warp 1) or |d_lat| (warp 2) ----
        const float* src = (warp == 1) ? dlon : dlat;
        const float4* Pa = reinterpret_cast<const float4*>(src + (size_t)row * S_DIM);
        #pragma unroll 2
        for (int it = 0; it < S_DIM / 128; ++it) {
            float4 a = Pa[it * 32 + lane];
            float a0 = fabsf(a.x), a1 = fabsf(a.y), a2 = fabsf(a.z), a3 = fabsf(a.w);
            bool p0 = a0 <= thr, p1 = a1 <= thr, p2 = a2 <= thr, p3 = a3 <= thr;
            unsigned base = (unsigned)(it * 128) + (unsigned)lane * 4u;
            if (__any_sync(FULLM, p0 | p1)) {
                try_append(p0, a0, base + 0u, buf, cnt, thr, lane);
                try_append(p1, a1, base + 1u, buf, cnt, thr, lane);
            }
            if (__any_sync(FULLM, p2 | p3)) {
                try_append(p2, a2, base + 2u, buf, cnt, thr, lane);
                try_append(p3, a3, base + 3u, buf, cnt, thr, lane);
            }
        }
        __syncwarp();
        select_sorted(buf, cnt, NH, lane);
        const size_t obase = (warp == 1) ? OFF_ILON : OFF_ILAT;
        if (lane < NH) {
            unsigned idx = (unsigned)buf[lane];
            out[obase + (size_t)row * NH + lane] = (float)idx;
        }
    }
}

extern "C" void kernel_launch(void* const* d_in, const int* in_sizes, int n_in,
                              void* d_out, int out_size) {
    (void)in_sizes; (void)n_in; (void)out_size;
    const float* x    = (const float*)d_in[0];
    const float* dlon = (const float*)d_in[1];
    const float* dlat = (const float*)d_in[2];
    nn_topk_kernel<<<T_DIM, 96>>>(x, dlon, dlat, (float*)d_out);
}